// round 13
// baseline (speedup 1.0000x reference)
#include <cuda_runtime.h>
#include <cuda_bf16.h>
#include <cstdint>

#define FULL 0xFFFFFFFFu

constexpr int DM   = 64;     // model dim (K)
constexpr int NC   = 128;    // 2 heads * 64 (N)
constexpr int DEG  = 8;
constexpr int TILE = 128;    // nodes per CTA (M tile)

// ---------------- device scratch (no runtime allocation) -------------------
__device__ __align__(16) __nv_bfloat16 g_GT_hi[NC * DM];  // GT[n][k] = G[k][n]
__device__ __align__(16) __nv_bfloat16 g_GT_lo[NC * DM];
__device__ float g_v[NC];

// ---------------- smem layout (dynamic, bytes from base) --------------------
constexpr int STRB   = 144;
constexpr int TBYTES = 128 * STRB;           // 18432
constexpr int SM_V   = 0;                    // 128 floats
constexpr int SM_AHI = 1024;
constexpr int SM_ALO = SM_AHI + TBYTES;      // 19456
constexpr int SM_BHI = SM_ALO + TBYTES;      // 37888
constexpr int SM_BLO = SM_BHI + TBYTES;      // 56320
constexpr int SMEM_BYTES = SM_BLO + TBYTES;  // 74752
// w staging reuses the A/B region after MMA completes:
constexpr int SM_WSH   = 1024;
constexpr int WSTRIDE  = 136;                // floats per w row (2-lane LDS conflict-free)
// w region ends at 1024 + 128*136*4 = 70656 <= 74752

// ---------------- ptx helpers ------------------------------------------------
__device__ __forceinline__ uint32_t smem_u32(const void* p) {
    uint32_t a;
    asm("{ .reg .u64 t; cvta.to.shared.u64 t, %1; cvt.u32.u64 %0, t; }" : "=r"(a) : "l"(p));
    return a;
}
__device__ __forceinline__ void ldsm_x4(uint32_t* r, uint32_t addr) {
    asm volatile("ldmatrix.sync.aligned.m8n8.x4.shared.b16 {%0,%1,%2,%3}, [%4];"
                 : "=r"(r[0]), "=r"(r[1]), "=r"(r[2]), "=r"(r[3]) : "r"(addr));
}
__device__ __forceinline__ void mma16816(float* c, const uint32_t* a, uint32_t b0, uint32_t b1) {
    asm volatile(
        "mma.sync.aligned.m16n8k16.row.col.f32.bf16.bf16.f32 "
        "{%0,%1,%2,%3}, {%4,%5,%6,%7}, {%8,%9}, {%0,%1,%2,%3};"
        : "+f"(c[0]), "+f"(c[1]), "+f"(c[2]), "+f"(c[3])
        : "r"(a[0]), "r"(a[1]), "r"(a[2]), "r"(a[3]), "r"(b0), "r"(b1));
}

// bf16 split helpers
__device__ __forceinline__ uint32_t split2(float a, float b, float& la, float& lb) {
    __nv_bfloat16 ha = __float2bfloat16(a), hb = __float2bfloat16(b);
    la = a - __bfloat162float(ha);
    lb = b - __bfloat162float(hb);
    __nv_bfloat162 p = __halves2bfloat162(ha, hb);
    return *reinterpret_cast<uint32_t*>(&p);
}
__device__ __forceinline__ uint32_t pack2(float a, float b) {
    __nv_bfloat162 p = __floats2bfloat162_rn(a, b);
    return *reinterpret_cast<uint32_t*>(&p);
}

// ---------------------------------------------------------------------------
// Prologue: M_h = A_h^T B_h, emitted transposed as bf16 hi/lo:
//   GT[(h*64+e)][d] = M_h[d][e];  v[h*64+e] = sum_t B_h[t][e]*b[h*192+t].
// ---------------------------------------------------------------------------
__global__ void __launch_bounds__(256) prologue_kernel(const float* __restrict__ W,
                                                       const float* __restrict__ b) {
    const int h  = blockIdx.x >> 3;
    const int d0 = (blockIdx.x & 7) * 8;
    __shared__ float Bs[64][64];
    __shared__ float As[64][8];
    const int tid = threadIdx.x;

    const float4* Wk = (const float4*)(W + (h * 192 + 64) * 64);
    float4* Bs4 = (float4*)Bs;
    for (int i = tid; i < 1024; i += 256) Bs4[i] = Wk[i];
    const float* Wq = W + (h * 192) * 64;
    if (tid < 128) {
        int t = tid >> 1, j = (tid & 1) * 4;
        *(float4*)&As[t][j] = *(const float4*)&Wq[t * 64 + d0 + j];
    }
    __syncthreads();

    const int e  = tid & 63;
    const int dj = tid >> 6;  // 0..3
    float a0 = 0.f, a1 = 0.f;
#pragma unroll 8
    for (int t = 0; t < 64; t++) {
        float bv = Bs[t][e];
        a0 += As[t][dj] * bv;
        a1 += As[t][dj + 4] * bv;
    }
    const int row = h * 64 + e;
    {
        __nv_bfloat16 hi = __float2bfloat16(a0);
        g_GT_hi[row * 64 + d0 + dj] = hi;
        g_GT_lo[row * 64 + d0 + dj] = __float2bfloat16(a0 - __bfloat162float(hi));
    }
    {
        __nv_bfloat16 hi = __float2bfloat16(a1);
        g_GT_hi[row * 64 + d0 + dj + 4] = hi;
        g_GT_lo[row * 64 + d0 + dj + 4] = __float2bfloat16(a1 - __bfloat162float(hi));
    }
    if (d0 == 0 && dj == 0) {
        float s = 0.f;
#pragma unroll 8
        for (int t = 0; t < 64; t++) s += Bs[t][e] * b[h * 192 + t];
        g_v[row] = s;
    }
}

// ---------------------------------------------------------------------------
// Fused kernel, 256 threads / CTA, 2 CTAs / SM (proven point)
// ---------------------------------------------------------------------------
__device__ __forceinline__ float dot4(float4 a, float4 b) {
    return a.x * b.x + a.y * b.y + a.z * b.z + a.w * b.w;
}

__global__ void __launch_bounds__(256, 2) fused_kernel(const float* __restrict__ x,
                                                       const int* __restrict__ ei,
                                                       float* __restrict__ out,
                                                       int n, int E) {
    extern __shared__ char smem[];
    const uint32_t sb = smem_u32(smem);
    const int tid  = threadIdx.x;
    const int lane = tid & 31;
    const int wid  = tid >> 5;
    const int rowBase = blockIdx.x * TILE;

    float* vsh = (float*)(smem + SM_V);

    // ---- load B = GT hi/lo ----
    {
        const uint4* gth = (const uint4*)g_GT_hi;
        const uint4* gtl = (const uint4*)g_GT_lo;
        for (int i = tid; i < 1024; i += 256) {
            int r = i >> 3, c = i & 7;
            int off = r * STRB + c * 16;
            *(uint4*)(smem + SM_BHI + off) = gth[i];
            *(uint4*)(smem + SM_BLO + off) = gtl[i];
        }
    }
    // ---- convert x tile into bf16 hi/lo ----
    {
        const float4* x4 = (const float4*)x;
        for (int i = tid; i < 1024; i += 256) {
            int r = i >> 3, c = i & 7;
            int gr = rowBase + r;
            float4 f0 = make_float4(0.f, 0.f, 0.f, 0.f), f1 = f0;
            if (gr < n) { f0 = x4[gr * 16 + c * 2]; f1 = x4[gr * 16 + c * 2 + 1]; }
            float l0, l1, l2, l3, l4, l5, l6, l7;
            uint4 hi, lo;
            hi.x = split2(f0.x, f0.y, l0, l1);
            hi.y = split2(f0.z, f0.w, l2, l3);
            hi.z = split2(f1.x, f1.y, l4, l5);
            hi.w = split2(f1.z, f1.w, l6, l7);
            lo.x = pack2(l0, l1); lo.y = pack2(l2, l3);
            lo.z = pack2(l4, l5); lo.w = pack2(l6, l7);
            int off = r * STRB + c * 16;
            *(uint4*)(smem + SM_AHI + off) = hi;
            *(uint4*)(smem + SM_ALO + off) = lo;
        }
    }
    if (tid < NC) vsh[tid] = g_v[tid];
    __syncthreads();

    // ---- MMA: 2-D warp partition: wr=wid>>1 (32 rows), wc=wid&1 (64 cols) ----
    const int wr = wid >> 1;
    const int wc = wid & 1;
    float acc[16][4];
#pragma unroll
    for (int f = 0; f < 16; f++) { acc[f][0] = acc[f][1] = acc[f][2] = acc[f][3] = 0.f; }

    const uint32_t aOff0 = (uint32_t)((wr * 32 + (lane & 15)) * STRB + ((lane >> 4) << 4));
    const uint32_t aOff1 = aOff0 + 16 * STRB;
    const uint32_t bOffL =
        (uint32_t)(((lane & 7) + ((lane >> 4) << 3)) * STRB + (((lane >> 3) & 1) << 4));

#pragma unroll
    for (int k = 0; k < 4; k++) {
        uint32_t ah0[4], ah1[4], al0[4], al1[4];
        ldsm_x4(ah0, sb + SM_AHI + aOff0 + k * 32);
        ldsm_x4(ah1, sb + SM_AHI + aOff1 + k * 32);
        ldsm_x4(al0, sb + SM_ALO + aOff0 + k * 32);
        ldsm_x4(al1, sb + SM_ALO + aOff1 + k * 32);
#pragma unroll
        for (int nb = 0; nb < 4; nb++) {
            const uint32_t bRow = (uint32_t)((wc * 64 + nb * 16) * STRB) + bOffL + k * 32;
            uint32_t bh[4], bl[4];
            ldsm_x4(bh, sb + SM_BHI + bRow);
            mma16816(acc[nb * 2 + 0], ah0, bh[0], bh[1]);
            mma16816(acc[nb * 2 + 1], ah0, bh[2], bh[3]);
            mma16816(acc[8 + nb * 2 + 0], ah1, bh[0], bh[1]);
            mma16816(acc[8 + nb * 2 + 1], ah1, bh[2], bh[3]);
            mma16816(acc[nb * 2 + 0], al0, bh[0], bh[1]);
            mma16816(acc[nb * 2 + 1], al0, bh[2], bh[3]);
            mma16816(acc[8 + nb * 2 + 0], al1, bh[0], bh[1]);
            mma16816(acc[8 + nb * 2 + 1], al1, bh[2], bh[3]);
            ldsm_x4(bl, sb + SM_BLO + bRow);
            mma16816(acc[nb * 2 + 0], ah0, bl[0], bl[1]);
            mma16816(acc[nb * 2 + 1], ah0, bl[2], bl[3]);
            mma16816(acc[8 + nb * 2 + 0], ah1, bl[0], bl[1]);
            mma16816(acc[8 + nb * 2 + 1], ah1, bl[2], bl[3]);
        }
    }

    __syncthreads();  // all MMA smem reads done; safe to overlay w

    // ---- epilogue: w = D + v into smem (WSTRIDE=136) ----
    float* wsh = (float*)(smem + SM_WSH);
    {
        const int g = lane >> 2, tig = lane & 3;
#pragma unroll
        for (int rb = 0; rb < 2; rb++) {
            const int row0 = wr * 32 + rb * 16 + g;
#pragma unroll
            for (int nb = 0; nb < 4; nb++) {
#pragma unroll
                for (int j = 0; j < 2; j++) {
                    const int col = wc * 64 + nb * 16 + j * 8 + 2 * tig;
                    const float* a = acc[rb * 8 + nb * 2 + j];
                    float v0 = vsh[col], v1 = vsh[col + 1];
                    *(float2*)&wsh[row0 * WSTRIDE + col] = make_float2(a[0] + v0, a[1] + v1);
                    *(float2*)&wsh[(row0 + 8) * WSTRIDE + col] = make_float2(a[2] + v0, a[3] + v1);
                }
            }
        }
    }
    __syncthreads();  // w fully written (rows span warps)

    // ---- score+softmax v6: warp -> 16 nodes, lane = (u=node lane>>1, t=half).
    //      w half-rows register-resident with interleaved (2i+t) float4 index:
    //      each lane pair covers 32B contiguous per LDG/LDS -> 100% sectors.
    //      ONE shfl_xor(1) per head per neighbor: 16 shfl/warp (was 512). ----
    const int* cols = ei + E;
    const int r0 = wid * 16;
    const int u = lane >> 1;
    const int t = lane & 1;
    const int r = r0 + u;
    const int node = rowBase + r;
    const bool active = node < n;

    // w registers: head0 = wr4[2i+t], head1 = wr4[16+2i+t], i=0..7
    const float4* wr4 = (const float4*)(wsh + r * WSTRIDE);
    float4 wA[8], wB[8];
#pragma unroll
    for (int i = 0; i < 8; i++) {
        wA[i] = wr4[2 * i + t];
        wB[i] = wr4[16 + 2 * i + t];
    }

    int cj[8];
    if (active) {
        const int4* cp = (const int4*)(cols + (size_t)node * DEG);
        int4 ca = cp[0], cb = cp[1];
        cj[0] = ca.x; cj[1] = ca.y; cj[2] = ca.z; cj[3] = ca.w;
        cj[4] = cb.x; cj[5] = cb.y; cj[6] = cb.z; cj[7] = cb.w;
    } else {
#pragma unroll
        for (int j = 0; j < 8; j++) cj[j] = 0;
    }

    float s0[8], s1[8];
#pragma unroll
    for (int j = 0; j < 8; j++) {
        const float4* xp = (const float4*)(x + (size_t)cj[j] * DM);
        float p0 = 0.f, p1 = 0.f;
#pragma unroll
        for (int i = 0; i < 8; i++) {
            float4 xv = xp[2 * i + t];
            p0 += dot4(wA[i], xv);
            p1 += dot4(wB[i], xv);
        }
        p0 += __shfl_xor_sync(FULL, p0, 1);
        p1 += __shfl_xor_sync(FULL, p1, 1);
        s0[j] = p0 * 8.0f;
        s1[j] = p1 * 8.0f;
    }

    // softmax in registers (both lanes of the pair hold identical s)
    float m0 = fmaxf(fmaxf(fmaxf(s0[0], s0[1]), fmaxf(s0[2], s0[3])),
                     fmaxf(fmaxf(s0[4], s0[5]), fmaxf(s0[6], s0[7])));
    float m1 = fmaxf(fmaxf(fmaxf(s1[0], s1[1]), fmaxf(s1[2], s1[3])),
                     fmaxf(fmaxf(s1[4], s1[5]), fmaxf(s1[6], s1[7])));
    float z0 = 0.f, z1 = 0.f;
#pragma unroll
    for (int j = 0; j < 8; j++) {
        z0 += __expf(s0[j] - m0);
        z1 += __expf(s1[j] - m1);
    }
    float i0 = 0.5f / z0, i1 = 0.5f / z1;

    // lane t writes out floats [4t, 4t+4): one float4 per lane, 32B/node pair
    if (active) {
        float o[4];
#pragma unroll
        for (int k = 0; k < 4; k++) {
            float sa = t ? s0[4 + k] : s0[k];
            float sbv = t ? s1[4 + k] : s1[k];
            o[k] = __expf(sa - m0) * i0 + __expf(sbv - m1) * i1;
        }
        ((float4*)(out + (size_t)node * DEG))[t] = make_float4(o[0], o[1], o[2], o[3]);
    }
}

// ---------------------------------------------------------------------------
extern "C" void kernel_launch(void* const* d_in, const int* in_sizes, int n_in,
                              void* d_out, int out_size) {
    const float* x = (const float*)d_in[0];
    const float* W = (const float*)d_in[1];
    const float* b = (const float*)d_in[2];
    const int* ei  = (const int*)d_in[3];
    float* out = (float*)d_out;

    const int n = in_sizes[0] / DM;
    const int E = in_sizes[3] / 2;

    static bool attr_set = false;
    if (!attr_set) {
        cudaFuncSetAttribute(fused_kernel, cudaFuncAttributeMaxDynamicSharedMemorySize, SMEM_BYTES);
        attr_set = true;
    }

    prologue_kernel<<<16, 256>>>(W, b);
    fused_kernel<<<(n + TILE - 1) / TILE, 256, SMEM_BYTES>>>(x, ei, out, n, E);
}

// round 14
// speedup vs baseline: 1.1251x; 1.1251x over previous
#include <cuda_runtime.h>
#include <cuda_bf16.h>
#include <cstdint>

#define FULL 0xFFFFFFFFu

constexpr int DM   = 64;     // model dim (K)
constexpr int NC   = 128;    // 2 heads * 64 (N)
constexpr int DEG  = 8;
constexpr int TILE = 128;    // nodes per CTA (M tile)

// ---------------- device scratch (no runtime allocation) -------------------
__device__ __align__(16) __nv_bfloat16 g_GT_hi[NC * DM];  // GT[n][k] = G[k][n]
__device__ __align__(16) __nv_bfloat16 g_GT_lo[NC * DM];
__device__ float g_v[NC];

// ---------------- smem layout (dynamic, bytes from base) --------------------
constexpr int STRB   = 144;
constexpr int TBYTES = 128 * STRB;           // 18432
constexpr int SM_V   = 0;                    // 128 floats
constexpr int SM_AHI = 1024;
constexpr int SM_ALO = SM_AHI + TBYTES;      // 19456
constexpr int SM_BHI = SM_ALO + TBYTES;      // 37888
constexpr int SM_BLO = SM_BHI + TBYTES;      // 56320  (A/B end 74752)
constexpr int SM_CJ  = 74752;                // 128 nodes * 8 ints = 4096B
constexpr int SMEM_BYTES = SM_CJ + TILE * DEG * 4;  // 78848 (x2 CTAs ok, as R5-R10)
// w staging reuses the A/B region after MMA completes:
constexpr int SM_WSH   = 1024;
constexpr int WSTRIDE  = 132;                // floats per w row (ends at 68608)

// ---------------- ptx helpers ------------------------------------------------
__device__ __forceinline__ uint32_t smem_u32(const void* p) {
    uint32_t a;
    asm("{ .reg .u64 t; cvta.to.shared.u64 t, %1; cvt.u32.u64 %0, t; }" : "=r"(a) : "l"(p));
    return a;
}
__device__ __forceinline__ void ldsm_x4(uint32_t* r, uint32_t addr) {
    asm volatile("ldmatrix.sync.aligned.m8n8.x4.shared.b16 {%0,%1,%2,%3}, [%4];"
                 : "=r"(r[0]), "=r"(r[1]), "=r"(r[2]), "=r"(r[3]) : "r"(addr));
}
__device__ __forceinline__ void mma16816(float* c, const uint32_t* a, uint32_t b0, uint32_t b1) {
    asm volatile(
        "mma.sync.aligned.m16n8k16.row.col.f32.bf16.bf16.f32 "
        "{%0,%1,%2,%3}, {%4,%5,%6,%7}, {%8,%9}, {%0,%1,%2,%3};"
        : "+f"(c[0]), "+f"(c[1]), "+f"(c[2]), "+f"(c[3])
        : "r"(a[0]), "r"(a[1]), "r"(a[2]), "r"(a[3]), "r"(b0), "r"(b1));
}

// bf16 split helpers
__device__ __forceinline__ uint32_t split2(float a, float b, float& la, float& lb) {
    __nv_bfloat16 ha = __float2bfloat16(a), hb = __float2bfloat16(b);
    la = a - __bfloat162float(ha);
    lb = b - __bfloat162float(hb);
    __nv_bfloat162 p = __halves2bfloat162(ha, hb);
    return *reinterpret_cast<uint32_t*>(&p);
}
__device__ __forceinline__ uint32_t pack2(float a, float b) {
    __nv_bfloat162 p = __floats2bfloat162_rn(a, b);
    return *reinterpret_cast<uint32_t*>(&p);
}

// pick element 2t (resp. 2t+1) of 8 register values without dynamic indexing
__device__ __forceinline__ float sel4(float v0, float v1, float v2, float v3, int t) {
    float lo = (t & 1) ? v1 : v0;
    float hi = (t & 1) ? v3 : v2;
    return (t & 2) ? hi : lo;
}

// ---------------------------------------------------------------------------
// Prologue: M_h = A_h^T B_h, emitted transposed as bf16 hi/lo:
//   GT[(h*64+e)][d] = M_h[d][e];  v[h*64+e] = sum_t B_h[t][e]*b[h*192+t].
// ---------------------------------------------------------------------------
__global__ void __launch_bounds__(256) prologue_kernel(const float* __restrict__ W,
                                                       const float* __restrict__ b) {
    const int h  = blockIdx.x >> 3;
    const int d0 = (blockIdx.x & 7) * 8;
    __shared__ float Bs[64][64];
    __shared__ float As[64][8];
    const int tid = threadIdx.x;

    const float4* Wk = (const float4*)(W + (h * 192 + 64) * 64);
    float4* Bs4 = (float4*)Bs;
    for (int i = tid; i < 1024; i += 256) Bs4[i] = Wk[i];
    const float* Wq = W + (h * 192) * 64;
    if (tid < 128) {
        int t = tid >> 1, j = (tid & 1) * 4;
        *(float4*)&As[t][j] = *(const float4*)&Wq[t * 64 + d0 + j];
    }
    __syncthreads();

    const int e  = tid & 63;
    const int dj = tid >> 6;  // 0..3
    float a0 = 0.f, a1 = 0.f;
#pragma unroll 8
    for (int t = 0; t < 64; t++) {
        float bv = Bs[t][e];
        a0 += As[t][dj] * bv;
        a1 += As[t][dj + 4] * bv;
    }
    const int row = h * 64 + e;
    {
        __nv_bfloat16 hi = __float2bfloat16(a0);
        g_GT_hi[row * 64 + d0 + dj] = hi;
        g_GT_lo[row * 64 + d0 + dj] = __float2bfloat16(a0 - __bfloat162float(hi));
    }
    {
        __nv_bfloat16 hi = __float2bfloat16(a1);
        g_GT_hi[row * 64 + d0 + dj + 4] = hi;
        g_GT_lo[row * 64 + d0 + dj + 4] = __float2bfloat16(a1 - __bfloat162float(hi));
    }
    if (d0 == 0 && dj == 0) {
        float s = 0.f;
#pragma unroll 8
        for (int t = 0; t < 64; t++) s += Bs[t][e] * b[h * 192 + t];
        g_v[row] = s;
    }
}

// ---------------------------------------------------------------------------
// Fused kernel, 256 threads / CTA, 2 CTAs / SM (proven point, R11 base)
// ---------------------------------------------------------------------------
__device__ __forceinline__ float dot4(float4 a, float4 b) {
    return a.x * b.x + a.y * b.y + a.z * b.z + a.w * b.w;
}

__global__ void __launch_bounds__(256, 2) fused_kernel(const float* __restrict__ x,
                                                       const int* __restrict__ ei,
                                                       float* __restrict__ out,
                                                       int n, int E) {
    extern __shared__ char smem[];
    const uint32_t sb = smem_u32(smem);
    const int tid  = threadIdx.x;
    const int lane = tid & 31;
    const int wid  = tid >> 5;
    const int rowBase = blockIdx.x * TILE;

    float* vsh = (float*)(smem + SM_V);
    const int* cols = ei + E;

    // ---- stage neighbor indices into smem (latency hides behind loader+MMA) ----
    {
        int4* scj = (int4*)(smem + SM_CJ);
        // int4 #tid covers cols of node rowBase + tid/2
        int4 v = make_int4(0, 0, 0, 0);
        if (rowBase + (tid >> 1) < n)
            v = ((const int4*)(cols + (size_t)rowBase * DEG))[tid];
        scj[tid] = v;
    }

    // ---- load B = GT hi/lo ----
    {
        const uint4* gth = (const uint4*)g_GT_hi;
        const uint4* gtl = (const uint4*)g_GT_lo;
        for (int i = tid; i < 1024; i += 256) {
            int r = i >> 3, c = i & 7;
            int off = r * STRB + c * 16;
            *(uint4*)(smem + SM_BHI + off) = gth[i];
            *(uint4*)(smem + SM_BLO + off) = gtl[i];
        }
    }
    // ---- convert x tile into bf16 hi/lo ----
    {
        const float4* x4 = (const float4*)x;
        for (int i = tid; i < 1024; i += 256) {
            int r = i >> 3, c = i & 7;
            int gr = rowBase + r;
            float4 f0 = make_float4(0.f, 0.f, 0.f, 0.f), f1 = f0;
            if (gr < n) { f0 = x4[gr * 16 + c * 2]; f1 = x4[gr * 16 + c * 2 + 1]; }
            float l0, l1, l2, l3, l4, l5, l6, l7;
            uint4 hi, lo;
            hi.x = split2(f0.x, f0.y, l0, l1);
            hi.y = split2(f0.z, f0.w, l2, l3);
            hi.z = split2(f1.x, f1.y, l4, l5);
            hi.w = split2(f1.z, f1.w, l6, l7);
            lo.x = pack2(l0, l1); lo.y = pack2(l2, l3);
            lo.z = pack2(l4, l5); lo.w = pack2(l6, l7);
            int off = r * STRB + c * 16;
            *(uint4*)(smem + SM_AHI + off) = hi;
            *(uint4*)(smem + SM_ALO + off) = lo;
        }
    }
    if (tid < NC) vsh[tid] = g_v[tid];
    __syncthreads();

    // ---- MMA: 2-D warp partition: wr=wid>>1 (32 rows), wc=wid&1 (64 cols) ----
    const int wr = wid >> 1;
    const int wc = wid & 1;
    float acc[16][4];
#pragma unroll
    for (int f = 0; f < 16; f++) { acc[f][0] = acc[f][1] = acc[f][2] = acc[f][3] = 0.f; }

    const uint32_t aOff0 = (uint32_t)((wr * 32 + (lane & 15)) * STRB + ((lane >> 4) << 4));
    const uint32_t aOff1 = aOff0 + 16 * STRB;
    const uint32_t bOffL =
        (uint32_t)(((lane & 7) + ((lane >> 4) << 3)) * STRB + (((lane >> 3) & 1) << 4));

#pragma unroll
    for (int k = 0; k < 4; k++) {
        uint32_t ah0[4], ah1[4], al0[4], al1[4];
        ldsm_x4(ah0, sb + SM_AHI + aOff0 + k * 32);
        ldsm_x4(ah1, sb + SM_AHI + aOff1 + k * 32);
        ldsm_x4(al0, sb + SM_ALO + aOff0 + k * 32);
        ldsm_x4(al1, sb + SM_ALO + aOff1 + k * 32);
#pragma unroll
        for (int nb = 0; nb < 4; nb++) {
            const uint32_t bRow = (uint32_t)((wc * 64 + nb * 16) * STRB) + bOffL + k * 32;
            uint32_t bh[4], bl[4];
            ldsm_x4(bh, sb + SM_BHI + bRow);
            mma16816(acc[nb * 2 + 0], ah0, bh[0], bh[1]);
            mma16816(acc[nb * 2 + 1], ah0, bh[2], bh[3]);
            mma16816(acc[8 + nb * 2 + 0], ah1, bh[0], bh[1]);
            mma16816(acc[8 + nb * 2 + 1], ah1, bh[2], bh[3]);
            mma16816(acc[nb * 2 + 0], al0, bh[0], bh[1]);
            mma16816(acc[nb * 2 + 1], al0, bh[2], bh[3]);
            mma16816(acc[8 + nb * 2 + 0], al1, bh[0], bh[1]);
            mma16816(acc[8 + nb * 2 + 1], al1, bh[2], bh[3]);
            ldsm_x4(bl, sb + SM_BLO + bRow);
            mma16816(acc[nb * 2 + 0], ah0, bl[0], bl[1]);
            mma16816(acc[nb * 2 + 1], ah0, bl[2], bl[3]);
            mma16816(acc[8 + nb * 2 + 0], ah1, bl[0], bl[1]);
            mma16816(acc[8 + nb * 2 + 1], ah1, bl[2], bl[3]);
        }
    }

    __syncthreads();  // all MMA smem reads done; safe to overlay w

    // ---- epilogue: w = D + v into smem ----
    float* wsh = (float*)(smem + SM_WSH);
    {
        const int g = lane >> 2, tig = lane & 3;
#pragma unroll
        for (int rb = 0; rb < 2; rb++) {
            const int row0 = wr * 32 + rb * 16 + g;
#pragma unroll
            for (int nb = 0; nb < 4; nb++) {
#pragma unroll
                for (int j = 0; j < 2; j++) {
                    const int col = wc * 64 + nb * 16 + j * 8 + 2 * tig;
                    const float* a = acc[rb * 8 + nb * 2 + j];
                    float v0 = vsh[col], v1 = vsh[col + 1];
                    *(float2*)&wsh[row0 * WSTRIDE + col] = make_float2(a[0] + v0, a[1] + v1);
                    *(float2*)&wsh[(row0 + 8) * WSTRIDE + col] = make_float2(a[2] + v0, a[3] + v1);
                }
            }
        }
    }
    __syncthreads();  // w fully written (rows span warps)

    // ---- score+softmax v4+cj: warp -> 16 nodes in two groups of 8.
    //      lane = (q=node-in-group lane>>2, t=quarter lane&3).
    //      cj from SMEM (prefetched in loader); x prefetch issued BEFORE the
    //      w register loads so gather latency overlaps the LDS.
    //      Sector-efficient xp[4*i + t] indexing throughout. ----
    const int4* scj = (const int4*)(smem + SM_CJ);
    const int r0 = wid * 16;
    const int q = lane >> 2;
    const int t = lane & 3;

#pragma unroll
    for (int h = 0; h < 2; h++) {
        const int r = r0 + h * 8 + q;
        const int node = rowBase + r;
        const bool active = node < n;

        // neighbor indices from smem (broadcast within the 4-lane group)
        int4 ca = scj[2 * r], cb = scj[2 * r + 1];
        int cj[8];
        cj[0] = ca.x; cj[1] = ca.y; cj[2] = ca.z; cj[3] = ca.w;
        cj[4] = cb.x; cj[5] = cb.y; cj[6] = cb.z; cj[7] = cb.w;

        // depth-2 prefetch, sector-efficient loads — issued before w loads
        float4 xA[4], xB[4];
        {
            const float4* xp = (const float4*)(x + (size_t)cj[0] * DM);
#pragma unroll
            for (int i = 0; i < 4; i++) xA[i] = xp[4 * i + t];
            const float4* xq = (const float4*)(x + (size_t)cj[1] * DM);
#pragma unroll
            for (int i = 0; i < 4; i++) xB[i] = xq[4 * i + t];
        }

        // w chunks under the (4i+t) permutation; head1 at +16 float4s
        const float4* wr4 = (const float4*)(wsh + r * WSTRIDE);
        float4 w0[4], w1[4];
#pragma unroll
        for (int i = 0; i < 4; i++) {
            w0[i] = wr4[4 * i + t];
            w1[i] = wr4[16 + 4 * i + t];
        }

        float s0[8], s1[8];
#pragma unroll
        for (int j = 0; j < 8; j++) {
            float4 c0, c1, c2, c3;
            if ((j & 1) == 0) { c0 = xA[0]; c1 = xA[1]; c2 = xA[2]; c3 = xA[3]; }
            else              { c0 = xB[0]; c1 = xB[1]; c2 = xB[2]; c3 = xB[3]; }
            if (j + 2 < 8) {
                const float4* xn = (const float4*)(x + (size_t)cj[j + 2] * DM);
                if ((j & 1) == 0) {
#pragma unroll
                    for (int i = 0; i < 4; i++) xA[i] = xn[4 * i + t];
                } else {
#pragma unroll
                    for (int i = 0; i < 4; i++) xB[i] = xn[4 * i + t];
                }
            }
            float p0 = (dot4(w0[0], c0) + dot4(w0[1], c1)) + (dot4(w0[2], c2) + dot4(w0[3], c3));
            float p1 = (dot4(w1[0], c0) + dot4(w1[1], c1)) + (dot4(w1[2], c2) + dot4(w1[3], c3));
            p0 += __shfl_xor_sync(FULL, p0, 1);
            p0 += __shfl_xor_sync(FULL, p0, 2);
            p1 += __shfl_xor_sync(FULL, p1, 1);
            p1 += __shfl_xor_sync(FULL, p1, 2);
            s0[j] = p0 * 8.0f;
            s1[j] = p1 * 8.0f;
        }

        // softmax in registers (all 4 lanes of the group hold identical s)
        float m0 = fmaxf(fmaxf(fmaxf(s0[0], s0[1]), fmaxf(s0[2], s0[3])),
                         fmaxf(fmaxf(s0[4], s0[5]), fmaxf(s0[6], s0[7])));
        float m1 = fmaxf(fmaxf(fmaxf(s1[0], s1[1]), fmaxf(s1[2], s1[3])),
                         fmaxf(fmaxf(s1[4], s1[5]), fmaxf(s1[6], s1[7])));
        float e0[8], e1[8];
#pragma unroll
        for (int j = 0; j < 8; j++) {
            e0[j] = __expf(s0[j] - m0);
            e1[j] = __expf(s1[j] - m1);
        }
        float z0 = (e0[0] + e0[1]) + (e0[2] + e0[3]) + (e0[4] + e0[5]) + (e0[6] + e0[7]);
        float z1 = (e1[0] + e1[1]) + (e1[2] + e1[3]) + (e1[4] + e1[5]) + (e1[6] + e1[7]);
        float i0 = 0.5f / z0, i1 = 0.5f / z1;

        // lane t writes outputs 2t, 2t+1
        float a0 = sel4(e0[0], e0[2], e0[4], e0[6], t);
        float a1 = sel4(e0[1], e0[3], e0[5], e0[7], t);
        float b0 = sel4(e1[0], e1[2], e1[4], e1[6], t);
        float b1 = sel4(e1[1], e1[3], e1[5], e1[7], t);
        if (active) {
            float2 o = make_float2(a0 * i0 + b0 * i1, a1 * i0 + b1 * i1);
            ((float2*)(out + (size_t)node * DEG))[t] = o;
        }
    }
}

// ---------------------------------------------------------------------------
extern "C" void kernel_launch(void* const* d_in, const int* in_sizes, int n_in,
                              void* d_out, int out_size) {
    const float* x = (const float*)d_in[0];
    const float* W = (const float*)d_in[1];
    const float* b = (const float*)d_in[2];
    const int* ei  = (const int*)d_in[3];
    float* out = (float*)d_out;

    const int n = in_sizes[0] / DM;
    const int E = in_sizes[3] / 2;

    static bool attr_set = false;
    if (!attr_set) {
        cudaFuncSetAttribute(fused_kernel, cudaFuncAttributeMaxDynamicSharedMemorySize, SMEM_BYTES);
        attr_set = true;
    }

    prologue_kernel<<<16, 256>>>(W, b);
    fused_kernel<<<(n + TILE - 1) / TILE, 256, SMEM_BYTES>>>(x, ei, out, n, E);
}

// round 15
// speedup vs baseline: 1.1302x; 1.0045x over previous
#include <cuda_runtime.h>
#include <cuda_bf16.h>
#include <cstdint>

#define FULL 0xFFFFFFFFu

constexpr int DM   = 64;     // model dim (K)
constexpr int NC   = 128;    // 2 heads * 64 (N)
constexpr int DEG  = 8;
constexpr int TILE = 128;    // nodes per CTA (M tile)

// ---------------- device scratch (no runtime allocation) -------------------
__device__ __align__(16) __nv_bfloat16 g_GT_hi[NC * DM];  // GT[n][k] = G[k][n]
__device__ __align__(16) __nv_bfloat16 g_GT_lo[NC * DM];
__device__ float g_v[NC];

// ---------------- smem layout (dynamic, bytes from base) --------------------
constexpr int STRB   = 144;
constexpr int TBYTES = 128 * STRB;           // 18432
constexpr int SM_V   = 0;                    // 128 floats
constexpr int SM_AHI = 1024;
constexpr int SM_ALO = SM_AHI + TBYTES;      // 19456
constexpr int SM_BHI = SM_ALO + TBYTES;      // 37888
constexpr int SM_BLO = SM_BHI + TBYTES;      // 56320  (A/B end 74752)
constexpr int SM_CJ  = 74752;                // 128 nodes * 8 ints = 4096B
constexpr int SMEM_BYTES = SM_CJ + TILE * DEG * 4;  // 78848 (2 CTAs/SM ok)
// w staging reuses the A/B region after MMA completes:
constexpr int SM_WSH   = 1024;
constexpr int WSTRIDE  = 132;                // floats per w row (ends at 68608)

// ---------------- ptx helpers ------------------------------------------------
__device__ __forceinline__ uint32_t smem_u32(const void* p) {
    uint32_t a;
    asm("{ .reg .u64 t; cvta.to.shared.u64 t, %1; cvt.u32.u64 %0, t; }" : "=r"(a) : "l"(p));
    return a;
}
__device__ __forceinline__ void ldsm_x4(uint32_t* r, uint32_t addr) {
    asm volatile("ldmatrix.sync.aligned.m8n8.x4.shared.b16 {%0,%1,%2,%3}, [%4];"
                 : "=r"(r[0]), "=r"(r[1]), "=r"(r[2]), "=r"(r[3]) : "r"(addr));
}
__device__ __forceinline__ void mma16816(float* c, const uint32_t* a, uint32_t b0, uint32_t b1) {
    asm volatile(
        "mma.sync.aligned.m16n8k16.row.col.f32.bf16.bf16.f32 "
        "{%0,%1,%2,%3}, {%4,%5,%6,%7}, {%8,%9}, {%0,%1,%2,%3};"
        : "+f"(c[0]), "+f"(c[1]), "+f"(c[2]), "+f"(c[3])
        : "r"(a[0]), "r"(a[1]), "r"(a[2]), "r"(a[3]), "r"(b0), "r"(b1));
}

// bf16 split helpers
__device__ __forceinline__ uint32_t split2(float a, float b, float& la, float& lb) {
    __nv_bfloat16 ha = __float2bfloat16(a), hb = __float2bfloat16(b);
    la = a - __bfloat162float(ha);
    lb = b - __bfloat162float(hb);
    __nv_bfloat162 p = __halves2bfloat162(ha, hb);
    return *reinterpret_cast<uint32_t*>(&p);
}
__device__ __forceinline__ uint32_t pack2(float a, float b) {
    __nv_bfloat162 p = __floats2bfloat162_rn(a, b);
    return *reinterpret_cast<uint32_t*>(&p);
}

// select element idx (0..7) of 8 register values via predicated selects
__device__ __forceinline__ float sel8(const float* s, int idx) {
    float a = (idx & 1) ? s[1] : s[0];
    float b = (idx & 1) ? s[3] : s[2];
    float c = (idx & 1) ? s[5] : s[4];
    float d = (idx & 1) ? s[7] : s[6];
    float ab = (idx & 2) ? b : a;
    float cd = (idx & 2) ? d : c;
    return (idx & 4) ? cd : ab;
}

// ---------------------------------------------------------------------------
// Prologue: M_h = A_h^T B_h, emitted transposed as bf16 hi/lo:
//   GT[(h*64+e)][d] = M_h[d][e];  v[h*64+e] = sum_t B_h[t][e]*b[h*192+t].
// ---------------------------------------------------------------------------
__global__ void __launch_bounds__(256) prologue_kernel(const float* __restrict__ W,
                                                       const float* __restrict__ b) {
    const int h  = blockIdx.x >> 3;
    const int d0 = (blockIdx.x & 7) * 8;
    __shared__ float Bs[64][64];
    __shared__ float As[64][8];
    const int tid = threadIdx.x;

    const float4* Wk = (const float4*)(W + (h * 192 + 64) * 64);
    float4* Bs4 = (float4*)Bs;
    for (int i = tid; i < 1024; i += 256) Bs4[i] = Wk[i];
    const float* Wq = W + (h * 192) * 64;
    if (tid < 128) {
        int t = tid >> 1, j = (tid & 1) * 4;
        *(float4*)&As[t][j] = *(const float4*)&Wq[t * 64 + d0 + j];
    }
    __syncthreads();

    const int e  = tid & 63;
    const int dj = tid >> 6;  // 0..3
    float a0 = 0.f, a1 = 0.f;
#pragma unroll 8
    for (int t = 0; t < 64; t++) {
        float bv = Bs[t][e];
        a0 += As[t][dj] * bv;
        a1 += As[t][dj + 4] * bv;
    }
    const int row = h * 64 + e;
    {
        __nv_bfloat16 hi = __float2bfloat16(a0);
        g_GT_hi[row * 64 + d0 + dj] = hi;
        g_GT_lo[row * 64 + d0 + dj] = __float2bfloat16(a0 - __bfloat162float(hi));
    }
    {
        __nv_bfloat16 hi = __float2bfloat16(a1);
        g_GT_hi[row * 64 + d0 + dj + 4] = hi;
        g_GT_lo[row * 64 + d0 + dj + 4] = __float2bfloat16(a1 - __bfloat162float(hi));
    }
    if (d0 == 0 && dj == 0) {
        float s = 0.f;
#pragma unroll 8
        for (int t = 0; t < 64; t++) s += Bs[t][e] * b[h * 192 + t];
        g_v[row] = s;
    }
}

// ---------------------------------------------------------------------------
// Fused kernel, 256 threads / CTA, 2 CTAs / SM (proven point, R14 base)
// ---------------------------------------------------------------------------
__device__ __forceinline__ float dot4(float4 a, float4 b) {
    return a.x * b.x + a.y * b.y + a.z * b.z + a.w * b.w;
}

__global__ void __launch_bounds__(256, 2) fused_kernel(const float* __restrict__ x,
                                                       const int* __restrict__ ei,
                                                       float* __restrict__ out,
                                                       int n, int E) {
    extern __shared__ char smem[];
    const uint32_t sb = smem_u32(smem);
    const int tid  = threadIdx.x;
    const int lane = tid & 31;
    const int wid  = tid >> 5;
    const int rowBase = blockIdx.x * TILE;

    float* vsh = (float*)(smem + SM_V);
    const int* cols = ei + E;

    // ---- stage neighbor indices into smem (latency hides behind loader+MMA) ----
    {
        int4* scj = (int4*)(smem + SM_CJ);
        int4 v = make_int4(0, 0, 0, 0);
        if (rowBase + (tid >> 1) < n)
            v = ((const int4*)(cols + (size_t)rowBase * DEG))[tid];
        scj[tid] = v;
    }

    // ---- load B = GT hi/lo ----
    {
        const uint4* gth = (const uint4*)g_GT_hi;
        const uint4* gtl = (const uint4*)g_GT_lo;
        for (int i = tid; i < 1024; i += 256) {
            int r = i >> 3, c = i & 7;
            int off = r * STRB + c * 16;
            *(uint4*)(smem + SM_BHI + off) = gth[i];
            *(uint4*)(smem + SM_BLO + off) = gtl[i];
        }
    }
    // ---- convert x tile into bf16 hi/lo ----
    {
        const float4* x4 = (const float4*)x;
        for (int i = tid; i < 1024; i += 256) {
            int r = i >> 3, c = i & 7;
            int gr = rowBase + r;
            float4 f0 = make_float4(0.f, 0.f, 0.f, 0.f), f1 = f0;
            if (gr < n) { f0 = x4[gr * 16 + c * 2]; f1 = x4[gr * 16 + c * 2 + 1]; }
            float l0, l1, l2, l3, l4, l5, l6, l7;
            uint4 hi, lo;
            hi.x = split2(f0.x, f0.y, l0, l1);
            hi.y = split2(f0.z, f0.w, l2, l3);
            hi.z = split2(f1.x, f1.y, l4, l5);
            hi.w = split2(f1.z, f1.w, l6, l7);
            lo.x = pack2(l0, l1); lo.y = pack2(l2, l3);
            lo.z = pack2(l4, l5); lo.w = pack2(l6, l7);
            int off = r * STRB + c * 16;
            *(uint4*)(smem + SM_AHI + off) = hi;
            *(uint4*)(smem + SM_ALO + off) = lo;
        }
    }
    if (tid < NC) vsh[tid] = g_v[tid];
    __syncthreads();

    // ---- MMA: 2-D warp partition: wr=wid>>1 (32 rows), wc=wid&1 (64 cols) ----
    const int wr = wid >> 1;
    const int wc = wid & 1;
    float acc[16][4];
#pragma unroll
    for (int f = 0; f < 16; f++) { acc[f][0] = acc[f][1] = acc[f][2] = acc[f][3] = 0.f; }

    const uint32_t aOff0 = (uint32_t)((wr * 32 + (lane & 15)) * STRB + ((lane >> 4) << 4));
    const uint32_t aOff1 = aOff0 + 16 * STRB;
    const uint32_t bOffL =
        (uint32_t)(((lane & 7) + ((lane >> 4) << 3)) * STRB + (((lane >> 3) & 1) << 4));

#pragma unroll
    for (int k = 0; k < 4; k++) {
        uint32_t ah0[4], ah1[4], al0[4], al1[4];
        ldsm_x4(ah0, sb + SM_AHI + aOff0 + k * 32);
        ldsm_x4(ah1, sb + SM_AHI + aOff1 + k * 32);
        ldsm_x4(al0, sb + SM_ALO + aOff0 + k * 32);
        ldsm_x4(al1, sb + SM_ALO + aOff1 + k * 32);
#pragma unroll
        for (int nb = 0; nb < 4; nb++) {
            const uint32_t bRow = (uint32_t)((wc * 64 + nb * 16) * STRB) + bOffL + k * 32;
            uint32_t bh[4], bl[4];
            ldsm_x4(bh, sb + SM_BHI + bRow);
            mma16816(acc[nb * 2 + 0], ah0, bh[0], bh[1]);
            mma16816(acc[nb * 2 + 1], ah0, bh[2], bh[3]);
            mma16816(acc[8 + nb * 2 + 0], ah1, bh[0], bh[1]);
            mma16816(acc[8 + nb * 2 + 1], ah1, bh[2], bh[3]);
            mma16816(acc[nb * 2 + 0], al0, bh[0], bh[1]);
            mma16816(acc[nb * 2 + 1], al0, bh[2], bh[3]);
            mma16816(acc[8 + nb * 2 + 0], al1, bh[0], bh[1]);
            mma16816(acc[8 + nb * 2 + 1], al1, bh[2], bh[3]);
            ldsm_x4(bl, sb + SM_BLO + bRow);
            mma16816(acc[nb * 2 + 0], ah0, bl[0], bl[1]);
            mma16816(acc[nb * 2 + 1], ah0, bl[2], bl[3]);
            mma16816(acc[8 + nb * 2 + 0], ah1, bl[0], bl[1]);
            mma16816(acc[8 + nb * 2 + 1], ah1, bl[2], bl[3]);
        }
    }

    __syncthreads();  // all MMA smem reads done; safe to overlay w

    // ---- epilogue: w = D + v into smem ----
    float* wsh = (float*)(smem + SM_WSH);
    {
        const int g = lane >> 2, tig = lane & 3;
#pragma unroll
        for (int rb = 0; rb < 2; rb++) {
            const int row0 = wr * 32 + rb * 16 + g;
#pragma unroll
            for (int nb = 0; nb < 4; nb++) {
#pragma unroll
                for (int j = 0; j < 2; j++) {
                    const int col = wc * 64 + nb * 16 + j * 8 + 2 * tig;
                    const float* a = acc[rb * 8 + nb * 2 + j];
                    float v0 = vsh[col], v1 = vsh[col + 1];
                    *(float2*)&wsh[row0 * WSTRIDE + col] = make_float2(a[0] + v0, a[1] + v1);
                    *(float2*)&wsh[(row0 + 8) * WSTRIDE + col] = make_float2(a[2] + v0, a[3] + v1);
                }
            }
        }
    }
    __syncthreads();  // w fully written (rows span warps)

    // ---- score+softmax v7: warp -> 16 nodes in 4 batches of 4.
    //      lane = (g = node-in-batch lane>>3, e = eighth lane&7).
    //      Per gather LDG instr, each 8-lane octet reads 128B CONTIGUOUS
    //      (exactly one L1 line) -> 1 wavefront per line (was 2).
    //      Lane owns dims [4e,4e+4) and [32+4e,+4) of both heads; reduce over
    //      the octet with 3 shfl per head. w still non-redundant from smem.
    const int4* scj = (const int4*)(smem + SM_CJ);
    const int r0 = wid * 16;
    const int g = lane >> 3;
    const int e = lane & 7;

#pragma unroll 1
    for (int b = 0; b < 4; b++) {
        const int r = r0 + b * 4 + g;
        const int node = rowBase + r;
        const bool active = node < n;

        // neighbor indices (broadcast within octet)
        int4 ca = scj[2 * r], cb2 = scj[2 * r + 1];
        int cj[8];
        cj[0] = ca.x; cj[1] = ca.y; cj[2] = ca.z; cj[3] = ca.w;
        cj[4] = cb2.x; cj[5] = cb2.y; cj[6] = cb2.z; cj[7] = cb2.w;

        // x prefetch, depth-2: each buffer = 2 float4 (floats [4e,4e+4) and
        // [32+4e,+4)). LDG addresses per octet: row*256 + 16e (+128) -> one
        // full 128B line per octet per instr.
        float4 xA0, xA1, xB0, xB1;
        {
            const float4* xp = (const float4*)(x + (size_t)cj[0] * DM);
            xA0 = xp[e]; xA1 = xp[8 + e];
            const float4* xq = (const float4*)(x + (size_t)cj[1] * DM);
            xB0 = xq[e]; xB1 = xq[8 + e];
        }

        // w chunks (same permutation as x)
        const float4* wr4 = (const float4*)(wsh + r * WSTRIDE);
        float4 w00 = wr4[e], w01 = wr4[8 + e];       // head 0
        float4 w10 = wr4[16 + e], w11 = wr4[24 + e]; // head 1

        float s0[8], s1[8];
#pragma unroll
        for (int j = 0; j < 8; j++) {
            float4 c0, c1;
            if ((j & 1) == 0) { c0 = xA0; c1 = xA1; }
            else              { c0 = xB0; c1 = xB1; }
            if (j + 2 < 8) {
                const float4* xn = (const float4*)(x + (size_t)cj[j + 2] * DM);
                if ((j & 1) == 0) { xA0 = xn[e]; xA1 = xn[8 + e]; }
                else              { xB0 = xn[e]; xB1 = xn[8 + e]; }
            }
            float p0 = dot4(w00, c0) + dot4(w01, c1);
            float p1 = dot4(w10, c0) + dot4(w11, c1);
            p0 += __shfl_xor_sync(FULL, p0, 1);
            p0 += __shfl_xor_sync(FULL, p0, 2);
            p0 += __shfl_xor_sync(FULL, p0, 4);
            p1 += __shfl_xor_sync(FULL, p1, 1);
            p1 += __shfl_xor_sync(FULL, p1, 2);
            p1 += __shfl_xor_sync(FULL, p1, 4);
            s0[j] = p0 * 8.0f;
            s1[j] = p1 * 8.0f;
        }

        // softmax in registers (all 8 octet lanes hold identical s)
        float m0 = fmaxf(fmaxf(fmaxf(s0[0], s0[1]), fmaxf(s0[2], s0[3])),
                         fmaxf(fmaxf(s0[4], s0[5]), fmaxf(s0[6], s0[7])));
        float m1 = fmaxf(fmaxf(fmaxf(s1[0], s1[1]), fmaxf(s1[2], s1[3])),
                         fmaxf(fmaxf(s1[4], s1[5]), fmaxf(s1[6], s1[7])));
        float z0 = 0.f, z1 = 0.f;
#pragma unroll
        for (int j = 0; j < 8; j++) {
            z0 += __expf(s0[j] - m0);
            z1 += __expf(s1[j] - m1);
        }
        float i0 = 0.5f / z0, i1 = 0.5f / z1;

        // lane e writes output element e of its node: warp store = 4 nodes x
        // 32B contiguous (nodes consecutive in g) = one 128B line.
        if (active) {
            float se0 = sel8(s0, e);
            float se1 = sel8(s1, e);
            out[(size_t)node * DEG + e] = __expf(se0 - m0) * i0 + __expf(se1 - m1) * i1;
        }
    }
}

// ---------------------------------------------------------------------------
extern "C" void kernel_launch(void* const* d_in, const int* in_sizes, int n_in,
                              void* d_out, int out_size) {
    const float* x = (const float*)d_in[0];
    const float* W = (const float*)d_in[1];
    const float* b = (const float*)d_in[2];
    const int* ei  = (const int*)d_in[3];
    float* out = (float*)d_out;

    const int n = in_sizes[0] / DM;
    const int E = in_sizes[3] / 2;

    static bool attr_set = false;
    if (!attr_set) {
        cudaFuncSetAttribute(fused_kernel, cudaFuncAttributeMaxDynamicSharedMemorySize, SMEM_BYTES);
        attr_set = true;
    }

    prologue_kernel<<<16, 256>>>(W, b);
    fused_kernel<<<(n + TILE - 1) / TILE, 256, SMEM_BYTES>>>(x, ei, out, n, E);
}

// round 16
// speedup vs baseline: 1.2169x; 1.0767x over previous
#include <cuda_runtime.h>
#include <cuda_bf16.h>
#include <cstdint>

#define FULL 0xFFFFFFFFu

constexpr int DM   = 64;     // model dim (K)
constexpr int NC   = 128;    // 2 heads * 64 (N)
constexpr int DEG  = 8;
constexpr int TILE = 128;    // nodes per CTA (M tile)

// ---------------- device scratch (no runtime allocation) -------------------
__device__ __align__(16) __nv_bfloat16 g_GT_hi[NC * DM];  // GT[n][k] = G[k][n]
__device__ __align__(16) __nv_bfloat16 g_GT_lo[NC * DM];
__device__ float g_v[NC];

// ---------------- smem layout (dynamic, bytes from base) --------------------
constexpr int STRB   = 144;
constexpr int TBYTES = 128 * STRB;           // 18432
constexpr int SM_V   = 0;                    // 128 floats
constexpr int SM_AHI = 1024;
constexpr int SM_ALO = SM_AHI + TBYTES;      // 19456
constexpr int SM_BHI = SM_ALO + TBYTES;      // 37888
constexpr int SM_BLO = SM_BHI + TBYTES;      // 56320  (A/B end 74752)
constexpr int SM_CJ  = 74752;                // 128 nodes * 8 ints = 4096B
constexpr int SMEM_BYTES = SM_CJ + TILE * DEG * 4;  // 78848 (2 CTAs/SM ok)
// w staging reuses the A/B region after MMA completes:
constexpr int SM_WSH   = 1024;
constexpr int WSTRIDE  = 132;                // floats per w row (ends at 68608)

// ---------------- ptx helpers ------------------------------------------------
__device__ __forceinline__ uint32_t smem_u32(const void* p) {
    uint32_t a;
    asm("{ .reg .u64 t; cvta.to.shared.u64 t, %1; cvt.u32.u64 %0, t; }" : "=r"(a) : "l"(p));
    return a;
}
__device__ __forceinline__ void ldsm_x4(uint32_t* r, uint32_t addr) {
    asm volatile("ldmatrix.sync.aligned.m8n8.x4.shared.b16 {%0,%1,%2,%3}, [%4];"
                 : "=r"(r[0]), "=r"(r[1]), "=r"(r[2]), "=r"(r[3]) : "r"(addr));
}
__device__ __forceinline__ void mma16816(float* c, const uint32_t* a, uint32_t b0, uint32_t b1) {
    asm volatile(
        "mma.sync.aligned.m16n8k16.row.col.f32.bf16.bf16.f32 "
        "{%0,%1,%2,%3}, {%4,%5,%6,%7}, {%8,%9}, {%0,%1,%2,%3};"
        : "+f"(c[0]), "+f"(c[1]), "+f"(c[2]), "+f"(c[3])
        : "r"(a[0]), "r"(a[1]), "r"(a[2]), "r"(a[3]), "r"(b0), "r"(b1));
}

// bf16 split helpers
__device__ __forceinline__ uint32_t split2(float a, float b, float& la, float& lb) {
    __nv_bfloat16 ha = __float2bfloat16(a), hb = __float2bfloat16(b);
    la = a - __bfloat162float(ha);
    lb = b - __bfloat162float(hb);
    __nv_bfloat162 p = __halves2bfloat162(ha, hb);
    return *reinterpret_cast<uint32_t*>(&p);
}
__device__ __forceinline__ uint32_t pack2(float a, float b) {
    __nv_bfloat162 p = __floats2bfloat162_rn(a, b);
    return *reinterpret_cast<uint32_t*>(&p);
}

// Butterfly reduce-scatter of 8 partials across an 8-lane octet (lane id e).
// On return: result = full sum over the octet of partial j == e.
__device__ __forceinline__ float reduce_scatter8(float* p, int e) {
    // stage mask=4: keep high half if (e&4), else low half
    float q[4];
#pragma unroll
    for (int i = 0; i < 4; i++) {
        float send = (e & 4) ? p[i] : p[i + 4];        // the half I discard
        float rcv = __shfl_xor_sync(FULL, send, 4);
        q[i] = ((e & 4) ? p[i + 4] : p[i]) + rcv;
    }
    // stage mask=2
    float r2[2];
#pragma unroll
    for (int i = 0; i < 2; i++) {
        float send = (e & 2) ? q[i] : q[i + 2];
        float rcv = __shfl_xor_sync(FULL, send, 2);
        r2[i] = ((e & 2) ? q[i + 2] : q[i]) + rcv;
    }
    // stage mask=1
    float send = (e & 1) ? r2[0] : r2[1];
    float rcv = __shfl_xor_sync(FULL, send, 1);
    return ((e & 1) ? r2[1] : r2[0]) + rcv;
}

// ---------------------------------------------------------------------------
// Prologue: M_h = A_h^T B_h, emitted transposed as bf16 hi/lo:
//   GT[(h*64+e)][d] = M_h[d][e];  v[h*64+e] = sum_t B_h[t][e]*b[h*192+t].
// ---------------------------------------------------------------------------
__global__ void __launch_bounds__(256) prologue_kernel(const float* __restrict__ W,
                                                       const float* __restrict__ b) {
    const int h  = blockIdx.x >> 3;
    const int d0 = (blockIdx.x & 7) * 8;
    __shared__ float Bs[64][64];
    __shared__ float As[64][8];
    const int tid = threadIdx.x;

    const float4* Wk = (const float4*)(W + (h * 192 + 64) * 64);
    float4* Bs4 = (float4*)Bs;
    for (int i = tid; i < 1024; i += 256) Bs4[i] = Wk[i];
    const float* Wq = W + (h * 192) * 64;
    if (tid < 128) {
        int t = tid >> 1, j = (tid & 1) * 4;
        *(float4*)&As[t][j] = *(const float4*)&Wq[t * 64 + d0 + j];
    }
    __syncthreads();

    const int e  = tid & 63;
    const int dj = tid >> 6;  // 0..3
    float a0 = 0.f, a1 = 0.f;
#pragma unroll 8
    for (int t = 0; t < 64; t++) {
        float bv = Bs[t][e];
        a0 += As[t][dj] * bv;
        a1 += As[t][dj + 4] * bv;
    }
    const int row = h * 64 + e;
    {
        __nv_bfloat16 hi = __float2bfloat16(a0);
        g_GT_hi[row * 64 + d0 + dj] = hi;
        g_GT_lo[row * 64 + d0 + dj] = __float2bfloat16(a0 - __bfloat162float(hi));
    }
    {
        __nv_bfloat16 hi = __float2bfloat16(a1);
        g_GT_hi[row * 64 + d0 + dj + 4] = hi;
        g_GT_lo[row * 64 + d0 + dj + 4] = __float2bfloat16(a1 - __bfloat162float(hi));
    }
    if (d0 == 0 && dj == 0) {
        float s = 0.f;
#pragma unroll 8
        for (int t = 0; t < 64; t++) s += Bs[t][e] * b[h * 192 + t];
        g_v[row] = s;
    }
}

// ---------------------------------------------------------------------------
// Fused kernel, 256 threads / CTA, 2 CTAs / SM (proven point, R15 base)
// ---------------------------------------------------------------------------
__device__ __forceinline__ float dot4(float4 a, float4 b) {
    return a.x * b.x + a.y * b.y + a.z * b.z + a.w * b.w;
}

__global__ void __launch_bounds__(256, 2) fused_kernel(const float* __restrict__ x,
                                                       const int* __restrict__ ei,
                                                       float* __restrict__ out,
                                                       int n, int E) {
    extern __shared__ char smem[];
    const uint32_t sb = smem_u32(smem);
    const int tid  = threadIdx.x;
    const int lane = tid & 31;
    const int wid  = tid >> 5;
    const int rowBase = blockIdx.x * TILE;

    float* vsh = (float*)(smem + SM_V);
    const int* cols = ei + E;

    // ---- stage neighbor indices into smem (latency hides behind loader+MMA) ----
    {
        int4* scj = (int4*)(smem + SM_CJ);
        int4 v = make_int4(0, 0, 0, 0);
        if (rowBase + (tid >> 1) < n)
            v = ((const int4*)(cols + (size_t)rowBase * DEG))[tid];
        scj[tid] = v;
    }

    // ---- load B = GT hi/lo ----
    {
        const uint4* gth = (const uint4*)g_GT_hi;
        const uint4* gtl = (const uint4*)g_GT_lo;
        for (int i = tid; i < 1024; i += 256) {
            int r = i >> 3, c = i & 7;
            int off = r * STRB + c * 16;
            *(uint4*)(smem + SM_BHI + off) = gth[i];
            *(uint4*)(smem + SM_BLO + off) = gtl[i];
        }
    }
    // ---- convert x tile into bf16 hi/lo ----
    {
        const float4* x4 = (const float4*)x;
        for (int i = tid; i < 1024; i += 256) {
            int r = i >> 3, c = i & 7;
            int gr = rowBase + r;
            float4 f0 = make_float4(0.f, 0.f, 0.f, 0.f), f1 = f0;
            if (gr < n) { f0 = x4[gr * 16 + c * 2]; f1 = x4[gr * 16 + c * 2 + 1]; }
            float l0, l1, l2, l3, l4, l5, l6, l7;
            uint4 hi, lo;
            hi.x = split2(f0.x, f0.y, l0, l1);
            hi.y = split2(f0.z, f0.w, l2, l3);
            hi.z = split2(f1.x, f1.y, l4, l5);
            hi.w = split2(f1.z, f1.w, l6, l7);
            lo.x = pack2(l0, l1); lo.y = pack2(l2, l3);
            lo.z = pack2(l4, l5); lo.w = pack2(l6, l7);
            int off = r * STRB + c * 16;
            *(uint4*)(smem + SM_AHI + off) = hi;
            *(uint4*)(smem + SM_ALO + off) = lo;
        }
    }
    if (tid < NC) vsh[tid] = g_v[tid];
    __syncthreads();

    // ---- MMA: 2-D warp partition: wr=wid>>1 (32 rows), wc=wid&1 (64 cols) ----
    const int wr = wid >> 1;
    const int wc = wid & 1;
    float acc[16][4];
#pragma unroll
    for (int f = 0; f < 16; f++) { acc[f][0] = acc[f][1] = acc[f][2] = acc[f][3] = 0.f; }

    const uint32_t aOff0 = (uint32_t)((wr * 32 + (lane & 15)) * STRB + ((lane >> 4) << 4));
    const uint32_t aOff1 = aOff0 + 16 * STRB;
    const uint32_t bOffL =
        (uint32_t)(((lane & 7) + ((lane >> 4) << 3)) * STRB + (((lane >> 3) & 1) << 4));

#pragma unroll
    for (int k = 0; k < 4; k++) {
        uint32_t ah0[4], ah1[4], al0[4], al1[4];
        ldsm_x4(ah0, sb + SM_AHI + aOff0 + k * 32);
        ldsm_x4(ah1, sb + SM_AHI + aOff1 + k * 32);
        ldsm_x4(al0, sb + SM_ALO + aOff0 + k * 32);
        ldsm_x4(al1, sb + SM_ALO + aOff1 + k * 32);
#pragma unroll
        for (int nb = 0; nb < 4; nb++) {
            const uint32_t bRow = (uint32_t)((wc * 64 + nb * 16) * STRB) + bOffL + k * 32;
            uint32_t bh[4], bl[4];
            ldsm_x4(bh, sb + SM_BHI + bRow);
            mma16816(acc[nb * 2 + 0], ah0, bh[0], bh[1]);
            mma16816(acc[nb * 2 + 1], ah0, bh[2], bh[3]);
            mma16816(acc[8 + nb * 2 + 0], ah1, bh[0], bh[1]);
            mma16816(acc[8 + nb * 2 + 1], ah1, bh[2], bh[3]);
            mma16816(acc[nb * 2 + 0], al0, bh[0], bh[1]);
            mma16816(acc[nb * 2 + 1], al0, bh[2], bh[3]);
            mma16816(acc[8 + nb * 2 + 0], al1, bh[0], bh[1]);
            mma16816(acc[8 + nb * 2 + 1], al1, bh[2], bh[3]);
            ldsm_x4(bl, sb + SM_BLO + bRow);
            mma16816(acc[nb * 2 + 0], ah0, bl[0], bl[1]);
            mma16816(acc[nb * 2 + 1], ah0, bl[2], bl[3]);
            mma16816(acc[8 + nb * 2 + 0], ah1, bl[0], bl[1]);
            mma16816(acc[8 + nb * 2 + 1], ah1, bl[2], bl[3]);
        }
    }

    __syncthreads();  // all MMA smem reads done; safe to overlay w

    // ---- epilogue: w = D + v into smem ----
    float* wsh = (float*)(smem + SM_WSH);
    {
        const int g = lane >> 2, tig = lane & 3;
#pragma unroll
        for (int rb = 0; rb < 2; rb++) {
            const int row0 = wr * 32 + rb * 16 + g;
#pragma unroll
            for (int nb = 0; nb < 4; nb++) {
#pragma unroll
                for (int j = 0; j < 2; j++) {
                    const int col = wc * 64 + nb * 16 + j * 8 + 2 * tig;
                    const float* a = acc[rb * 8 + nb * 2 + j];
                    float v0 = vsh[col], v1 = vsh[col + 1];
                    *(float2*)&wsh[row0 * WSTRIDE + col] = make_float2(a[0] + v0, a[1] + v1);
                    *(float2*)&wsh[(row0 + 8) * WSTRIDE + col] = make_float2(a[2] + v0, a[3] + v1);
                }
            }
        }
    }
    __syncthreads();  // w fully written (rows span warps)

    // ---- score+softmax v8: warp -> 16 nodes in 4 batches of 4.
    //      lane = (g = node-in-batch lane>>3, e = eighth lane&7).
    //      Gather: per LDG instr each octet reads one full 128B line (R15).
    //      Reduction: butterfly REDUCE-SCATTER (7 shfl/head) -> lane e holds
    //      s[e]; softmax lane-local: 1 exp/head + 3-shfl max + 3-shfl sum.
    //      shfl/warp 192->104, MUFU/lane 72->8 vs R15. ----
    const int4* scj = (const int4*)(smem + SM_CJ);
    const int r0 = wid * 16;
    const int g = lane >> 3;
    const int e = lane & 7;

#pragma unroll 1
    for (int b = 0; b < 4; b++) {
        const int r = r0 + b * 4 + g;
        const int node = rowBase + r;
        const bool active = node < n;

        // neighbor indices (broadcast within octet)
        int4 ca = scj[2 * r], cb2 = scj[2 * r + 1];
        int cj[8];
        cj[0] = ca.x; cj[1] = ca.y; cj[2] = ca.z; cj[3] = ca.w;
        cj[4] = cb2.x; cj[5] = cb2.y; cj[6] = cb2.z; cj[7] = cb2.w;

        // x prefetch, depth-2: lane covers floats [4e,4e+4) and [32+4e,+4)
        float4 xA0, xA1, xB0, xB1;
        {
            const float4* xp = (const float4*)(x + (size_t)cj[0] * DM);
            xA0 = xp[e]; xA1 = xp[8 + e];
            const float4* xq = (const float4*)(x + (size_t)cj[1] * DM);
            xB0 = xq[e]; xB1 = xq[8 + e];
        }

        // w chunks (same permutation as x)
        const float4* wr4 = (const float4*)(wsh + r * WSTRIDE);
        float4 w00 = wr4[e], w01 = wr4[8 + e];       // head 0
        float4 w10 = wr4[16 + e], w11 = wr4[24 + e]; // head 1

        // partials for all 8 neighbors (no per-j shuffles)
        float p0[8], p1[8];
#pragma unroll
        for (int j = 0; j < 8; j++) {
            float4 c0, c1;
            if ((j & 1) == 0) { c0 = xA0; c1 = xA1; }
            else              { c0 = xB0; c1 = xB1; }
            if (j + 2 < 8) {
                const float4* xn = (const float4*)(x + (size_t)cj[j + 2] * DM);
                if ((j & 1) == 0) { xA0 = xn[e]; xA1 = xn[8 + e]; }
                else              { xB0 = xn[e]; xB1 = xn[8 + e]; }
            }
            p0[j] = dot4(w00, c0) + dot4(w01, c1);
            p1[j] = dot4(w10, c0) + dot4(w11, c1);
        }

        // reduce-scatter: lane e ends with the full score of neighbor e
        float s0 = reduce_scatter8(p0, e) * 8.0f;
        float s1 = reduce_scatter8(p1, e) * 8.0f;

        // octet all-reduce max (3 shfl per head)
        float m0 = s0, m1 = s1;
        m0 = fmaxf(m0, __shfl_xor_sync(FULL, m0, 1));
        m0 = fmaxf(m0, __shfl_xor_sync(FULL, m0, 2));
        m0 = fmaxf(m0, __shfl_xor_sync(FULL, m0, 4));
        m1 = fmaxf(m1, __shfl_xor_sync(FULL, m1, 1));
        m1 = fmaxf(m1, __shfl_xor_sync(FULL, m1, 2));
        m1 = fmaxf(m1, __shfl_xor_sync(FULL, m1, 4));

        // one exp per head per lane; octet all-reduce sum for z
        float e0 = __expf(s0 - m0);
        float e1 = __expf(s1 - m1);
        float z0 = e0, z1 = e1;
        z0 += __shfl_xor_sync(FULL, z0, 1);
        z0 += __shfl_xor_sync(FULL, z0, 2);
        z0 += __shfl_xor_sync(FULL, z0, 4);
        z1 += __shfl_xor_sync(FULL, z1, 1);
        z1 += __shfl_xor_sync(FULL, z1, 2);
        z1 += __shfl_xor_sync(FULL, z1, 4);

        // lane e writes output element e of its node: warp store = 4 nodes x
        // 32B contiguous = one 128B line.
        if (active) {
            out[(size_t)node * DEG + e] = e0 * (0.5f / z0) + e1 * (0.5f / z1);
        }
    }
}

// ---------------------------------------------------------------------------
extern "C" void kernel_launch(void* const* d_in, const int* in_sizes, int n_in,
                              void* d_out, int out_size) {
    const float* x = (const float*)d_in[0];
    const float* W = (const float*)d_in[1];
    const float* b = (const float*)d_in[2];
    const int* ei  = (const int*)d_in[3];
    float* out = (float*)d_out;

    const int n = in_sizes[0] / DM;
    const int E = in_sizes[3] / 2;

    static bool attr_set = false;
    if (!attr_set) {
        cudaFuncSetAttribute(fused_kernel, cudaFuncAttributeMaxDynamicSharedMemorySize, SMEM_BYTES);
        attr_set = true;
    }

    prologue_kernel<<<16, 256>>>(W, b);
    fused_kernel<<<(n + TILE - 1) / TILE, 256, SMEM_BYTES>>>(x, ei, out, n, E);
}

// round 17
// speedup vs baseline: 1.2332x; 1.0134x over previous
#include <cuda_runtime.h>
#include <cuda_bf16.h>
#include <cstdint>

#define FULL 0xFFFFFFFFu

constexpr int DM   = 64;     // model dim (K)
constexpr int NC   = 128;    // 2 heads * 64 (N)
constexpr int DEG  = 8;
constexpr int TILE = 128;    // nodes per CTA (M tile)

// ---------------- device scratch (no runtime allocation) -------------------
__device__ __align__(16) __nv_bfloat16 g_GT_hi[NC * DM];  // GT[n][k] = G[k][n]
__device__ __align__(16) __nv_bfloat16 g_GT_lo[NC * DM];
__device__ float g_v[NC];

// ---------------- smem layout (dynamic, bytes from base) --------------------
constexpr int STRB   = 144;
constexpr int TBYTES = 128 * STRB;           // 18432
constexpr int SM_V   = 0;                    // 128 floats
constexpr int SM_AHI = 1024;
constexpr int SM_ALO = SM_AHI + TBYTES;      // 19456
constexpr int SM_BHI = SM_ALO + TBYTES;      // 37888
constexpr int SM_BLO = SM_BHI + TBYTES;      // 56320  (A/B end 74752)
constexpr int SM_CJ  = 74752;                // 128 nodes * 8 ints = 4096B
constexpr int SMEM_BYTES = SM_CJ + TILE * DEG * 4;  // 78848 (2 CTAs/SM ok)
// w staging reuses the A/B region after MMA completes:
constexpr int SM_WSH   = 1024;
constexpr int WSTRIDE  = 132;                // floats per w row (ends at 68608)

// ---------------- ptx helpers ------------------------------------------------
__device__ __forceinline__ uint32_t smem_u32(const void* p) {
    uint32_t a;
    asm("{ .reg .u64 t; cvta.to.shared.u64 t, %1; cvt.u32.u64 %0, t; }" : "=r"(a) : "l"(p));
    return a;
}
__device__ __forceinline__ void ldsm_x4(uint32_t* r, uint32_t addr) {
    asm volatile("ldmatrix.sync.aligned.m8n8.x4.shared.b16 {%0,%1,%2,%3}, [%4];"
                 : "=r"(r[0]), "=r"(r[1]), "=r"(r[2]), "=r"(r[3]) : "r"(addr));
}
__device__ __forceinline__ void mma16816(float* c, const uint32_t* a, uint32_t b0, uint32_t b1) {
    asm volatile(
        "mma.sync.aligned.m16n8k16.row.col.f32.bf16.bf16.f32 "
        "{%0,%1,%2,%3}, {%4,%5,%6,%7}, {%8,%9}, {%0,%1,%2,%3};"
        : "+f"(c[0]), "+f"(c[1]), "+f"(c[2]), "+f"(c[3])
        : "r"(a[0]), "r"(a[1]), "r"(a[2]), "r"(a[3]), "r"(b0), "r"(b1));
}

// bf16 split helpers
__device__ __forceinline__ uint32_t split2(float a, float b, float& la, float& lb) {
    __nv_bfloat16 ha = __float2bfloat16(a), hb = __float2bfloat16(b);
    la = a - __bfloat162float(ha);
    lb = b - __bfloat162float(hb);
    __nv_bfloat162 p = __halves2bfloat162(ha, hb);
    return *reinterpret_cast<uint32_t*>(&p);
}
__device__ __forceinline__ uint32_t pack2(float a, float b) {
    __nv_bfloat162 p = __floats2bfloat162_rn(a, b);
    return *reinterpret_cast<uint32_t*>(&p);
}

// Butterfly reduce-scatter of 8 partials across an 8-lane octet (lane id e).
// On return: result = full sum over the octet of partial j == e.
__device__ __forceinline__ float reduce_scatter8(float* p, int e) {
    float q[4];
#pragma unroll
    for (int i = 0; i < 4; i++) {
        float send = (e & 4) ? p[i] : p[i + 4];
        float rcv = __shfl_xor_sync(FULL, send, 4);
        q[i] = ((e & 4) ? p[i + 4] : p[i]) + rcv;
    }
    float r2[2];
#pragma unroll
    for (int i = 0; i < 2; i++) {
        float send = (e & 2) ? q[i] : q[i + 2];
        float rcv = __shfl_xor_sync(FULL, send, 2);
        r2[i] = ((e & 2) ? q[i + 2] : q[i]) + rcv;
    }
    float send = (e & 1) ? r2[0] : r2[1];
    float rcv = __shfl_xor_sync(FULL, send, 1);
    return ((e & 1) ? r2[1] : r2[0]) + rcv;
}

// ---------------------------------------------------------------------------
// Prologue: M_h = A_h^T B_h, emitted transposed as bf16 hi/lo:
//   GT[(h*64+e)][d] = M_h[d][e];  v[h*64+e] = sum_t B_h[t][e]*b[h*192+t].
// Triggers PDL completion at entry so the fused kernel can co-schedule and
// run its prologue-independent loader work.
// ---------------------------------------------------------------------------
__global__ void __launch_bounds__(256) prologue_kernel(const float* __restrict__ W,
                                                       const float* __restrict__ b) {
    cudaTriggerProgrammaticLaunchCompletion();

    const int h  = blockIdx.x >> 3;
    const int d0 = (blockIdx.x & 7) * 8;
    __shared__ float Bs[64][64];
    __shared__ float As[64][8];
    const int tid = threadIdx.x;

    const float4* Wk = (const float4*)(W + (h * 192 + 64) * 64);
    float4* Bs4 = (float4*)Bs;
    for (int i = tid; i < 1024; i += 256) Bs4[i] = Wk[i];
    const float* Wq = W + (h * 192) * 64;
    if (tid < 128) {
        int t = tid >> 1, j = (tid & 1) * 4;
        *(float4*)&As[t][j] = *(const float4*)&Wq[t * 64 + d0 + j];
    }
    __syncthreads();

    const int e  = tid & 63;
    const int dj = tid >> 6;  // 0..3
    float a0 = 0.f, a1 = 0.f;
#pragma unroll 8
    for (int t = 0; t < 64; t++) {
        float bv = Bs[t][e];
        a0 += As[t][dj] * bv;
        a1 += As[t][dj + 4] * bv;
    }
    const int row = h * 64 + e;
    {
        __nv_bfloat16 hi = __float2bfloat16(a0);
        g_GT_hi[row * 64 + d0 + dj] = hi;
        g_GT_lo[row * 64 + d0 + dj] = __float2bfloat16(a0 - __bfloat162float(hi));
    }
    {
        __nv_bfloat16 hi = __float2bfloat16(a1);
        g_GT_hi[row * 64 + d0 + dj + 4] = hi;
        g_GT_lo[row * 64 + d0 + dj + 4] = __float2bfloat16(a1 - __bfloat162float(hi));
    }
    if (d0 == 0 && dj == 0) {
        float s = 0.f;
#pragma unroll 8
        for (int t = 0; t < 64; t++) s += Bs[t][e] * b[h * 192 + t];
        g_v[row] = s;
    }
}

// ---------------------------------------------------------------------------
// Fused kernel, 256 threads / CTA, 2 CTAs / SM (R16 base + PDL overlap)
// ---------------------------------------------------------------------------
__device__ __forceinline__ float dot4(float4 a, float4 b) {
    return a.x * b.x + a.y * b.y + a.z * b.z + a.w * b.w;
}

__global__ void __launch_bounds__(256, 2) fused_kernel(const float* __restrict__ x,
                                                       const int* __restrict__ ei,
                                                       float* __restrict__ out,
                                                       int n, int E) {
    extern __shared__ char smem[];
    const uint32_t sb = smem_u32(smem);
    const int tid  = threadIdx.x;
    const int lane = tid & 31;
    const int wid  = tid >> 5;
    const int rowBase = blockIdx.x * TILE;

    float* vsh = (float*)(smem + SM_V);
    const int* cols = ei + E;

    // ---- prologue-INDEPENDENT work first (overlaps prologue via PDL) ----
    // stage neighbor indices into smem
    {
        int4* scj = (int4*)(smem + SM_CJ);
        int4 v = make_int4(0, 0, 0, 0);
        if (rowBase + (tid >> 1) < n)
            v = ((const int4*)(cols + (size_t)rowBase * DEG))[tid];
        scj[tid] = v;
    }
    // convert x tile into bf16 hi/lo
    {
        const float4* x4 = (const float4*)x;
        for (int i = tid; i < 1024; i += 256) {
            int r = i >> 3, c = i & 7;
            int gr = rowBase + r;
            float4 f0 = make_float4(0.f, 0.f, 0.f, 0.f), f1 = f0;
            if (gr < n) { f0 = x4[gr * 16 + c * 2]; f1 = x4[gr * 16 + c * 2 + 1]; }
            float l0, l1, l2, l3, l4, l5, l6, l7;
            uint4 hi, lo;
            hi.x = split2(f0.x, f0.y, l0, l1);
            hi.y = split2(f0.z, f0.w, l2, l3);
            hi.z = split2(f1.x, f1.y, l4, l5);
            hi.w = split2(f1.z, f1.w, l6, l7);
            lo.x = pack2(l0, l1); lo.y = pack2(l2, l3);
            lo.z = pack2(l4, l5); lo.w = pack2(l6, l7);
            int off = r * STRB + c * 16;
            *(uint4*)(smem + SM_AHI + off) = hi;
            *(uint4*)(smem + SM_ALO + off) = lo;
        }
    }

    // ---- wait for prologue's GT / v to be visible, then load them ----
    cudaGridDependencySynchronize();

    {
        const uint4* gth = (const uint4*)g_GT_hi;
        const uint4* gtl = (const uint4*)g_GT_lo;
        for (int i = tid; i < 1024; i += 256) {
            int r = i >> 3, c = i & 7;
            int off = r * STRB + c * 16;
            *(uint4*)(smem + SM_BHI + off) = gth[i];
            *(uint4*)(smem + SM_BLO + off) = gtl[i];
        }
    }
    if (tid < NC) vsh[tid] = g_v[tid];
    __syncthreads();

    // ---- MMA: 2-D warp partition: wr=wid>>1 (32 rows), wc=wid&1 (64 cols) ----
    const int wr = wid >> 1;
    const int wc = wid & 1;
    float acc[16][4];
#pragma unroll
    for (int f = 0; f < 16; f++) { acc[f][0] = acc[f][1] = acc[f][2] = acc[f][3] = 0.f; }

    const uint32_t aOff0 = (uint32_t)((wr * 32 + (lane & 15)) * STRB + ((lane >> 4) << 4));
    const uint32_t aOff1 = aOff0 + 16 * STRB;
    const uint32_t bOffL =
        (uint32_t)(((lane & 7) + ((lane >> 4) << 3)) * STRB + (((lane >> 3) & 1) << 4));

#pragma unroll
    for (int k = 0; k < 4; k++) {
        uint32_t ah0[4], ah1[4], al0[4], al1[4];
        ldsm_x4(ah0, sb + SM_AHI + aOff0 + k * 32);
        ldsm_x4(ah1, sb + SM_AHI + aOff1 + k * 32);
        ldsm_x4(al0, sb + SM_ALO + aOff0 + k * 32);
        ldsm_x4(al1, sb + SM_ALO + aOff1 + k * 32);
#pragma unroll
        for (int nb = 0; nb < 4; nb++) {
            const uint32_t bRow = (uint32_t)((wc * 64 + nb * 16) * STRB) + bOffL + k * 32;
            uint32_t bh[4], bl[4];
            ldsm_x4(bh, sb + SM_BHI + bRow);
            mma16816(acc[nb * 2 + 0], ah0, bh[0], bh[1]);
            mma16816(acc[nb * 2 + 1], ah0, bh[2], bh[3]);
            mma16816(acc[8 + nb * 2 + 0], ah1, bh[0], bh[1]);
            mma16816(acc[8 + nb * 2 + 1], ah1, bh[2], bh[3]);
            mma16816(acc[nb * 2 + 0], al0, bh[0], bh[1]);
            mma16816(acc[nb * 2 + 1], al0, bh[2], bh[3]);
            mma16816(acc[8 + nb * 2 + 0], al1, bh[0], bh[1]);
            mma16816(acc[8 + nb * 2 + 1], al1, bh[2], bh[3]);
            ldsm_x4(bl, sb + SM_BLO + bRow);
            mma16816(acc[nb * 2 + 0], ah0, bl[0], bl[1]);
            mma16816(acc[nb * 2 + 1], ah0, bl[2], bl[3]);
            mma16816(acc[8 + nb * 2 + 0], ah1, bl[0], bl[1]);
            mma16816(acc[8 + nb * 2 + 1], ah1, bl[2], bl[3]);
        }
    }

    __syncthreads();  // all MMA smem reads done; safe to overlay w

    // ---- epilogue: w = D + v into smem ----
    float* wsh = (float*)(smem + SM_WSH);
    {
        const int g = lane >> 2, tig = lane & 3;
#pragma unroll
        for (int rb = 0; rb < 2; rb++) {
            const int row0 = wr * 32 + rb * 16 + g;
#pragma unroll
            for (int nb = 0; nb < 4; nb++) {
#pragma unroll
                for (int j = 0; j < 2; j++) {
                    const int col = wc * 64 + nb * 16 + j * 8 + 2 * tig;
                    const float* a = acc[rb * 8 + nb * 2 + j];
                    float v0 = vsh[col], v1 = vsh[col + 1];
                    *(float2*)&wsh[row0 * WSTRIDE + col] = make_float2(a[0] + v0, a[1] + v1);
                    *(float2*)&wsh[(row0 + 8) * WSTRIDE + col] = make_float2(a[2] + v0, a[3] + v1);
                }
            }
        }
    }
    __syncthreads();  // w fully written (rows span warps)

    // ---- score+softmax v8: warp -> 16 nodes in 4 batches of 4.
    //      lane = (g = node-in-batch lane>>3, e = eighth lane&7). ----
    const int4* scj = (const int4*)(smem + SM_CJ);
    const int r0 = wid * 16;
    const int g = lane >> 3;
    const int e = lane & 7;

#pragma unroll 1
    for (int b = 0; b < 4; b++) {
        const int r = r0 + b * 4 + g;
        const int node = rowBase + r;
        const bool active = node < n;

        int4 ca = scj[2 * r], cb2 = scj[2 * r + 1];
        int cj[8];
        cj[0] = ca.x; cj[1] = ca.y; cj[2] = ca.z; cj[3] = ca.w;
        cj[4] = cb2.x; cj[5] = cb2.y; cj[6] = cb2.z; cj[7] = cb2.w;

        float4 xA0, xA1, xB0, xB1;
        {
            const float4* xp = (const float4*)(x + (size_t)cj[0] * DM);
            xA0 = xp[e]; xA1 = xp[8 + e];
            const float4* xq = (const float4*)(x + (size_t)cj[1] * DM);
            xB0 = xq[e]; xB1 = xq[8 + e];
        }

        const float4* wr4 = (const float4*)(wsh + r * WSTRIDE);
        float4 w00 = wr4[e], w01 = wr4[8 + e];       // head 0
        float4 w10 = wr4[16 + e], w11 = wr4[24 + e]; // head 1

        float p0[8], p1[8];
#pragma unroll
        for (int j = 0; j < 8; j++) {
            float4 c0, c1;
            if ((j & 1) == 0) { c0 = xA0; c1 = xA1; }
            else              { c0 = xB0; c1 = xB1; }
            if (j + 2 < 8) {
                const float4* xn = (const float4*)(x + (size_t)cj[j + 2] * DM);
                if ((j & 1) == 0) { xA0 = xn[e]; xA1 = xn[8 + e]; }
                else              { xB0 = xn[e]; xB1 = xn[8 + e]; }
            }
            p0[j] = dot4(w00, c0) + dot4(w01, c1);
            p1[j] = dot4(w10, c0) + dot4(w11, c1);
        }

        float s0 = reduce_scatter8(p0, e) * 8.0f;
        float s1 = reduce_scatter8(p1, e) * 8.0f;

        float m0 = s0, m1 = s1;
        m0 = fmaxf(m0, __shfl_xor_sync(FULL, m0, 1));
        m0 = fmaxf(m0, __shfl_xor_sync(FULL, m0, 2));
        m0 = fmaxf(m0, __shfl_xor_sync(FULL, m0, 4));
        m1 = fmaxf(m1, __shfl_xor_sync(FULL, m1, 1));
        m1 = fmaxf(m1, __shfl_xor_sync(FULL, m1, 2));
        m1 = fmaxf(m1, __shfl_xor_sync(FULL, m1, 4));

        float e0 = __expf(s0 - m0);
        float e1 = __expf(s1 - m1);
        float z0 = e0, z1 = e1;
        z0 += __shfl_xor_sync(FULL, z0, 1);
        z0 += __shfl_xor_sync(FULL, z0, 2);
        z0 += __shfl_xor_sync(FULL, z0, 4);
        z1 += __shfl_xor_sync(FULL, z1, 1);
        z1 += __shfl_xor_sync(FULL, z1, 2);
        z1 += __shfl_xor_sync(FULL, z1, 4);

        if (active) {
            out[(size_t)node * DEG + e] = e0 * (0.5f / z0) + e1 * (0.5f / z1);
        }
    }
}

// ---------------------------------------------------------------------------
extern "C" void kernel_launch(void* const* d_in, const int* in_sizes, int n_in,
                              void* d_out, int out_size) {
    const float* x = (const float*)d_in[0];
    const float* W = (const float*)d_in[1];
    const float* b = (const float*)d_in[2];
    const int* ei  = (const int*)d_in[3];
    float* out = (float*)d_out;

    const int n = in_sizes[0] / DM;
    const int E = in_sizes[3] / 2;

    static bool attr_set = false;
    if (!attr_set) {
        cudaFuncSetAttribute(fused_kernel, cudaFuncAttributeMaxDynamicSharedMemorySize, SMEM_BYTES);
        attr_set = true;
    }

    prologue_kernel<<<16, 256>>>(W, b);

    // PDL: fused kernel may launch as soon as prologue triggers; it performs
    // prologue-independent loading, then cudaGridDependencySynchronize()s.
    cudaLaunchConfig_t cfg = {};
    cfg.gridDim = dim3((n + TILE - 1) / TILE, 1, 1);
    cfg.blockDim = dim3(256, 1, 1);
    cfg.dynamicSmemBytes = SMEM_BYTES;
    cfg.stream = 0;
    cudaLaunchAttribute attrs[1];
    attrs[0].id = cudaLaunchAttributeProgrammaticStreamSerialization;
    attrs[0].val.programmaticStreamSerializationAllowed = 1;
    cfg.attrs = attrs;
    cfg.numAttrs = 1;
    cudaLaunchKernelEx(&cfg, fused_kernel, x, ei, out, n, E);
}